// round 1
// baseline (speedup 1.0000x reference)
#include <cuda_runtime.h>
#include <math.h>
#include <float.h>

#define BB   2
#define QN   30
#define WAYS 5
#define SHOTS 5
#define TOPK 5
#define DIMC 64
#define HWC  441
#define NSUP (WAYS*SHOTS)     // 25
#define LFE  15
#define SHW  (SHOTS*HWC)      // 2205
#define NTILE 7               // ceil(441/64)

// ---------------- scratch (device globals; no allocation allowed) ----------------
__device__ float g_qn[BB*QN*DIMC*HWC];      // normalized q  [b][q][d][h]
__device__ float g_sn[BB*NSUP*DIMC*HWC];    // normalized s  [b][n][d][h]
__device__ float g_qpool[BB*QN*DIMC];
__device__ float g_spool[BB*NSUP*DIMC];
__device__ float g_feats[BB*QN*LFE];        // cols 0..4 cos, 5..9 sim_l
__device__ float g_pix[BB*QN*WAYS*NTILE];   // pixel partial sums per h-tile

// sorted-descending top-5 insert (t[0] >= ... >= t[4])
__device__ __forceinline__ void ins5(float (&t)[TOPK], float v) {
    if (v > t[TOPK-1]) {
        float x = v;
        #pragma unroll
        for (int i = 0; i < TOPK; i++) {
            float hi = fmaxf(t[i], x);
            x = fminf(t[i], x);
            t[i] = hi;
        }
    }
}

// ---------------- kernel 1/2: L2-normalize over HW + mean pool ----------------
template<int IS_S>
__global__ void __launch_bounds__(256) knorm_kernel(const float* __restrict__ x) {
    const int n = blockIdx.x;
    float* __restrict__ xn   = IS_S ? g_sn : g_qn;
    float* __restrict__ pool = IS_S ? g_spool : g_qpool;
    const float* __restrict__ xr = x + (size_t)n * DIMC * HWC;
    float* __restrict__ xo = xn + (size_t)n * DIMC * HWC;
    const int warp = threadIdx.x >> 5, lane = threadIdx.x & 31;
    for (int d = warp; d < DIMC; d += 8) {
        const float* row = xr + d * HWC;
        float ss = 0.f, sm = 0.f;
        for (int h = lane; h < HWC; h += 32) {
            float v = row[h];
            ss = fmaf(v, v, ss);
            sm += v;
        }
        #pragma unroll
        for (int o = 16; o; o >>= 1) {
            ss += __shfl_xor_sync(0xffffffffu, ss, o);
            sm += __shfl_xor_sync(0xffffffffu, sm, o);
        }
        float inv = 1.0f / sqrtf(ss);
        for (int h = lane; h < HWC; h += 32) xo[d * HWC + h] = row[h] * inv;
        if (lane == 0) pool[n * DIMC + d] = sm * (1.0f / HWC);
    }
}

// ---------------- kernel 3: prototypes + cosine logits ----------------
__global__ void __launch_bounds__(256) kcos_kernel() {
    const int b = blockIdx.x, t = threadIdx.x;
    __shared__ float proto[WAYS * DIMC];
    __shared__ float pin[WAYS], qin[QN];
    for (int i = t; i < WAYS * DIMC; i += 256) {
        int w = i / DIMC, d = i - w * DIMC;
        float s = 0.f;
        #pragma unroll
        for (int k = 0; k < SHOTS; k++)
            s += g_spool[(b*NSUP + w*SHOTS + k)*DIMC + d];
        proto[i] = s * (1.0f / SHOTS);
    }
    __syncthreads();
    for (int i = t; i < WAYS + QN; i += 256) {
        if (i < WAYS) {
            float ss = 0.f;
            for (int d = 0; d < DIMC; d++) { float v = proto[i*DIMC + d]; ss = fmaf(v, v, ss); }
            pin[i] = 1.0f / sqrtf(ss);
        } else {
            int q = i - WAYS;
            float ss = 0.f;
            for (int d = 0; d < DIMC; d++) { float v = g_qpool[(b*QN + q)*DIMC + d]; ss = fmaf(v, v, ss); }
            qin[q] = 1.0f / sqrtf(ss);
        }
    }
    __syncthreads();
    for (int i = t; i < QN * WAYS; i += 256) {
        int q = i / WAYS, w = i - q * WAYS;
        float dot = 0.f;
        for (int d = 0; d < DIMC; d++)
            dot = fmaf(g_qpool[(b*QN + q)*DIMC + d], proto[w*DIMC + d], dot);
        g_feats[(b*QN + q)*LFE + w] = dot * qin[q] * pin[w];
    }
}

// ---------------- kernel 4: channel-level sim (64x320 GEMM, red 441, fused top-5) ----------------
__global__ void __launch_bounds__(256) kchan_kernel() {
    const int w = blockIdx.x, q = blockIdx.y, b = blockIdx.z;
    __shared__ __align__(16) float As[8][DIMC];            // [h_chunk][d]
    __shared__ __align__(16) float Bs[8][SHOTS*DIMC];      // [h_chunk][j]
    __shared__ float cand[DIMC][81];                       // padded stride 81
    const int t = threadIdx.x;
    const int ty = t >> 4, tx = t & 15;                    // rows d=ty*4.., cols j=tx*20..
    const float* __restrict__ qbase = g_qn + (size_t)(b*QN + q) * DIMC * HWC;
    const float* __restrict__ sbase = g_sn + (size_t)(b*NSUP + w*SHOTS) * DIMC * HWC;

    float acc[4][20];
    #pragma unroll
    for (int r = 0; r < 4; r++)
        #pragma unroll
        for (int c = 0; c < 20; c++) acc[r][c] = 0.f;

    for (int h0 = 0; h0 < HWC; h0 += 8) {
        __syncthreads();
        for (int idx = t; idx < 8*DIMC; idx += 256) {
            int i = idx >> 6, d = idx & 63;
            int h = h0 + i;
            As[i][d] = (h < HWC) ? qbase[d*HWC + h] : 0.f;
        }
        for (int idx = t; idx < 8*SHOTS*DIMC; idx += 256) {
            int i = idx / 320, j = idx - i*320;
            int h = h0 + i;
            Bs[i][j] = (h < HWC) ? sbase[(size_t)j*HWC + h] : 0.f;
        }
        __syncthreads();
        #pragma unroll
        for (int i = 0; i < 8; i++) {
            float4 av = *(const float4*)&As[i][ty*4];
            float a[4] = {av.x, av.y, av.z, av.w};
            float bb[20];
            #pragma unroll
            for (int c = 0; c < 5; c++)
                *(float4*)&bb[c*4] = *(const float4*)&Bs[i][tx*20 + c*4];
            #pragma unroll
            for (int r = 0; r < 4; r++)
                #pragma unroll
                for (int c = 0; c < 20; c++)
                    acc[r][c] = fmaf(a[r], bb[c], acc[r][c]);
        }
    }
    __syncthreads();
    #pragma unroll
    for (int r = 0; r < 4; r++) {
        float t5[TOPK];
        #pragma unroll
        for (int k = 0; k < TOPK; k++) t5[k] = -FLT_MAX;
        #pragma unroll
        for (int c = 0; c < 20; c++) ins5(t5, acc[r][c]);
        #pragma unroll
        for (int k = 0; k < TOPK; k++) cand[ty*4 + r][tx*TOPK + k] = t5[k];
    }
    __syncthreads();
    float mysum = 0.f;
    if (t < DIMC) {
        float t5[TOPK];
        #pragma unroll
        for (int k = 0; k < TOPK; k++) t5[k] = -FLT_MAX;
        #pragma unroll
        for (int i = 0; i < 80; i++) ins5(t5, cand[t][i]);
        mysum = t5[0] + t5[1] + t5[2] + t5[3] + t5[4];
    }
    __shared__ float red[2];
    if (t < DIMC) {
        #pragma unroll
        for (int o = 16; o; o >>= 1) mysum += __shfl_xor_sync(0xffffffffu, mysum, o);
        if ((t & 31) == 0) red[t >> 5] = mysum;
    }
    __syncthreads();
    if (t == 0) g_feats[(b*QN + q)*LFE + WAYS + w] = red[0] + red[1];
}

// ---------------- kernel 5: pixel-level sim (441x2205 GEMM, red 64, fused top-5) ----------------
__global__ void __launch_bounds__(256) kpix_kernel() {
    const int tile = blockIdx.x;                 // h-tile 0..6
    const int w = blockIdx.y;
    const int bq = blockIdx.z;                   // 0..59
    const int b = bq / QN, q = bq - b * QN;
    __shared__ __align__(16) float smem[2*64*64];     // As (16KB) + Bs (16KB)
    float (*As)[64] = (float(*)[64])smem;             // [k=d][m=h_local]
    float (*Bs)[64] = (float(*)[64])(smem + 64*64);   // [k=d][n=j_local]
    const int t = threadIdx.x;
    const int ty = t >> 4, tx = t & 15;          // thread owns 4 rows x 4 cols
    const int h0 = tile * 64;
    const float* __restrict__ qbase = g_qn + (size_t)(b*QN + q) * DIMC * HWC;
    const float* __restrict__ sbase = g_sn + (size_t)(b*NSUP + w*SHOTS) * DIMC * HWC;

    for (int idx = t; idx < 64*64; idx += 256) {
        int d = idx >> 6, i = idx & 63;
        int h = h0 + i;
        As[d][i] = (h < HWC) ? qbase[d*HWC + h] : 0.f;
    }

    float top[4][TOPK];
    #pragma unroll
    for (int r = 0; r < 4; r++)
        #pragma unroll
        for (int k = 0; k < TOPK; k++) top[r][k] = -FLT_MAX;

    for (int j0 = 0; j0 < SHW; j0 += 64) {
        __syncthreads();
        for (int idx = t; idx < 64*64; idx += 256) {
            int d = idx >> 6, jl = idx & 63;
            int j = j0 + jl;
            float v = 0.f;
            if (j < SHW) {
                int shot = j / HWC;
                int h2 = j - shot * HWC;
                v = sbase[(size_t)(shot*DIMC + d)*HWC + h2];
            }
            Bs[d][jl] = v;
        }
        __syncthreads();
        float acc[4][4];
        #pragma unroll
        for (int r = 0; r < 4; r++)
            #pragma unroll
            for (int c = 0; c < 4; c++) acc[r][c] = 0.f;
        #pragma unroll 16
        for (int k = 0; k < DIMC; k++) {
            float4 av = *(const float4*)&As[k][ty*4];
            float4 bv = *(const float4*)&Bs[k][tx*4];
            float a[4] = {av.x, av.y, av.z, av.w};
            float bb[4] = {bv.x, bv.y, bv.z, bv.w};
            #pragma unroll
            for (int r = 0; r < 4; r++)
                #pragma unroll
                for (int c = 0; c < 4; c++)
                    acc[r][c] = fmaf(a[r], bb[c], acc[r][c]);
        }
        #pragma unroll
        for (int c = 0; c < 4; c++) {
            bool valid = (j0 + tx*4 + c) < SHW;
            #pragma unroll
            for (int r = 0; r < 4; r++) {
                float v = valid ? acc[r][c] : -FLT_MAX;
                ins5(top[r], v);
            }
        }
    }

    __syncthreads();                                  // everyone done reading As/Bs
    float (*cand)[81] = (float(*)[81])smem;           // reuse smem (64*81 < 8192)
    #pragma unroll
    for (int r = 0; r < 4; r++)
        #pragma unroll
        for (int k = 0; k < TOPK; k++) cand[ty*4 + r][tx*TOPK + k] = top[r][k];
    __syncthreads();

    float rowsum = 0.f;
    if (t < 64) {
        int h = h0 + t;
        if (h < HWC) {
            float t5[TOPK];
            #pragma unroll
            for (int k = 0; k < TOPK; k++) t5[k] = -FLT_MAX;
            #pragma unroll
            for (int i = 0; i < 80; i++) ins5(t5, cand[t][i]);
            rowsum = t5[0] + t5[1] + t5[2] + t5[3] + t5[4];
        }
    }
    __shared__ float red[2];
    if (t < 64) {
        #pragma unroll
        for (int o = 16; o; o >>= 1) rowsum += __shfl_xor_sync(0xffffffffu, rowsum, o);
        if ((t & 31) == 0) red[t >> 5] = rowsum;
    }
    __syncthreads();
    if (t == 0) g_pix[((size_t)bq*WAYS + w)*NTILE + tile] = red[0] + red[1];
}

// ---------------- kernel 6: BN (batch stats) + dilated conv ----------------
__global__ void __launch_bounds__(256) kfin_kernel(const float* __restrict__ gamma,
                                                   const float* __restrict__ beta,
                                                   const float* __restrict__ cw,
                                                   float* __restrict__ out) {
    const int b = blockIdx.x;
    __shared__ float f[QN][LFE];
    __shared__ float mu[LFE], iv[LFE];
    const int t = threadIdx.x;
    for (int i = t; i < QN * WAYS; i += 256) {
        int q = i / WAYS, w = i - q * WAYS;
        const float* fr = &g_feats[(b*QN + q)*LFE];
        f[q][w]     = fr[w];
        f[q][5 + w] = fr[5 + w];
        float s = 0.f;
        #pragma unroll
        for (int j = 0; j < NTILE; j++)
            s += g_pix[((size_t)(b*QN + q)*WAYS + w)*NTILE + j];
        f[q][10 + w] = s;
    }
    __syncthreads();
    if (t < LFE) {
        float m = 0.f;
        for (int q = 0; q < QN; q++) m += f[q][t];
        m *= (1.0f / QN);
        float v = 0.f;
        for (int q = 0; q < QN; q++) { float d = f[q][t] - m; v = fmaf(d, d, v); }
        v *= (1.0f / QN);
        mu[t] = m;
        iv[t] = 1.0f / sqrtf(v + 1e-5f);
    }
    __syncthreads();
    float w0 = cw[0], w1 = cw[1], w2 = cw[2];
    for (int i = t; i < QN * WAYS; i += 256) {
        int q = i / WAYS, c = i - q * WAYS;
        float b0 = (f[q][c]      - mu[c])      * iv[c]      * gamma[c]      + beta[c];
        float b1 = (f[q][c + 5]  - mu[c + 5])  * iv[c + 5]  * gamma[c + 5]  + beta[c + 5];
        float b2 = (f[q][c + 10] - mu[c + 10]) * iv[c + 10] * gamma[c + 10] + beta[c + 10];
        out[(b*QN + q)*WAYS + c] = w0*b0 + w1*b1 + w2*b2;
    }
}

// ---------------- launch ----------------
extern "C" void kernel_launch(void* const* d_in, const int* in_sizes, int n_in,
                              void* d_out, int out_size) {
    const float* q     = (const float*)d_in[0];
    const float* s     = (const float*)d_in[1];
    const float* gamma = (const float*)d_in[2];
    const float* beta  = (const float*)d_in[3];
    const float* cw    = (const float*)d_in[4];
    float* out = (float*)d_out;

    knorm_kernel<0><<<BB*QN, 256>>>(q);
    knorm_kernel<1><<<BB*NSUP, 256>>>(s);
    kcos_kernel<<<BB, 256>>>();
    kchan_kernel<<<dim3(WAYS, QN, BB), 256>>>();
    kpix_kernel<<<dim3(NTILE, WAYS, BB*QN), 256>>>();
    kfin_kernel<<<BB, 256>>>(gamma, beta, cw, out);
}